// round 1
// baseline (speedup 1.0000x reference)
#include <cuda_runtime.h>
#include <math.h>
#include <math_constants.h>

// Problem constants (fixed by the reference)
#define Bn 4
#define Hn 16
#define Sn 2048
#define Dn 64
#define BHn (Bn*Hn)

// d_out layout: [output B*H*S*D floats][attn_weights B*H*S*S floats]
static const size_t OSZ = (size_t)Bn * Hn * Sn * Dn;   // 8388608
static const size_t WSZ = (size_t)Bn * Hn * Sn * Sn;   // 268435456

// ---------------------------------------------------------------------------
// Kernel 1: scores = (Q @ K^T) * 0.125, masked positions -> -inf
// grid (S/64, S/64, BH), block (16,16). 64x64 output tile, 4x4 per thread.
// ---------------------------------------------------------------------------
__global__ void qk_scores_kernel(const float* __restrict__ Q,
                                 const float* __restrict__ K,
                                 const int*   __restrict__ mask,
                                 float*       __restrict__ W)
{
    __shared__ float Qs[64][65];
    __shared__ float Ks[64][65];

    const int bh = blockIdx.z;
    const int q0 = blockIdx.x * 64;
    const int k0 = blockIdx.y * 64;
    const int b  = bh / Hn;

    const float* Qt = Q + ((size_t)bh * Sn + q0) * Dn;   // 64x64 contiguous
    const float* Kt = K + ((size_t)bh * Sn + k0) * Dn;   // 64x64 contiguous

    const int tx = threadIdx.x;            // 0..15
    const int ty = threadIdx.y;            // 0..15
    const int t  = ty * 16 + tx;           // 0..255

    #pragma unroll
    for (int i = t; i < 64 * 64; i += 256) {
        Qs[i >> 6][i & 63] = Qt[i];
        Ks[i >> 6][i & 63] = Kt[i];
    }
    __syncthreads();

    float acc[4][4];
    #pragma unroll
    for (int i = 0; i < 4; i++)
        #pragma unroll
        for (int j = 0; j < 4; j++) acc[i][j] = 0.0f;

    #pragma unroll 8
    for (int kk = 0; kk < 64; kk++) {
        float a[4], bv[4];
        #pragma unroll
        for (int i = 0; i < 4; i++) a[i]  = Qs[ty + i * 16][kk];
        #pragma unroll
        for (int j = 0; j < 4; j++) bv[j] = Ks[tx + j * 16][kk];
        #pragma unroll
        for (int i = 0; i < 4; i++)
            #pragma unroll
            for (int j = 0; j < 4; j++)
                acc[i][j] = fmaf(a[i], bv[j], acc[i][j]);
    }

    float* Wb = W + (size_t)bh * Sn * Sn;
    #pragma unroll
    for (int j = 0; j < 4; j++) {
        const int kc = k0 + tx + j * 16;
        const bool masked = (mask[b * Sn + kc] == 1);
        #pragma unroll
        for (int i = 0; i < 4; i++) {
            const int qr = q0 + ty + i * 16;
            float v = masked ? -CUDART_INF_F : acc[i][j] * 0.125f;
            Wb[(size_t)qr * Sn + kc] = v;
        }
    }
}

// ---------------------------------------------------------------------------
// Kernel 2: in-place row softmax over the last dim (S=2048).
// One block per row, 256 threads, 8 elems/thread held in registers.
// ---------------------------------------------------------------------------
__global__ void softmax_rows_kernel(float* __restrict__ W)
{
    float* p = W + (size_t)blockIdx.x * Sn;
    const int t = threadIdx.x;

    float v[8];
    float mx = -CUDART_INF_F;
    #pragma unroll
    for (int i = 0; i < 8; i++) {
        v[i] = p[t + i * 256];
        mx = fmaxf(mx, v[i]);
    }

    __shared__ float red[256];
    red[t] = mx;
    __syncthreads();
    #pragma unroll
    for (int s = 128; s > 0; s >>= 1) {
        if (t < s) red[t] = fmaxf(red[t], red[t + s]);
        __syncthreads();
    }
    mx = red[0];
    __syncthreads();

    float sum = 0.0f;
    #pragma unroll
    for (int i = 0; i < 8; i++) {
        v[i] = expf(v[i] - mx);   // exp(-inf - mx) == 0 for masked
        sum += v[i];
    }
    red[t] = sum;
    __syncthreads();
    #pragma unroll
    for (int s = 128; s > 0; s >>= 1) {
        if (t < s) red[t] += red[t + s];
        __syncthreads();
    }
    const float inv = 1.0f / red[0];

    #pragma unroll
    for (int i = 0; i < 8; i++) p[t + i * 256] = v[i] * inv;
}

// ---------------------------------------------------------------------------
// Kernel 3: O = attn_weights @ V.
// grid (S/64, BH), block (16,16). 64 (queries) x 64 (head dim) per block,
// loop over the S (key) dimension in 64-wide tiles. 4x4 per thread.
// ---------------------------------------------------------------------------
__global__ void av_kernel(const float* __restrict__ W,
                          const float* __restrict__ V,
                          float*       __restrict__ O)
{
    __shared__ float Ws[64][65];   // [q][k]
    __shared__ float Vs[64][65];   // [k][d]

    const int bh = blockIdx.y;
    const int q0 = blockIdx.x * 64;

    const float* Wb = W + (size_t)bh * Sn * Sn + (size_t)q0 * Sn;
    const float* Vb = V + (size_t)bh * Sn * Dn;

    const int tx = threadIdx.x;
    const int ty = threadIdx.y;
    const int t  = ty * 16 + tx;

    float acc[4][4];
    #pragma unroll
    for (int i = 0; i < 4; i++)
        #pragma unroll
        for (int j = 0; j < 4; j++) acc[i][j] = 0.0f;

    for (int k0 = 0; k0 < Sn; k0 += 64) {
        #pragma unroll
        for (int i = t; i < 64 * 64; i += 256) {
            const int r = i >> 6, c = i & 63;
            Ws[r][c] = Wb[(size_t)r * Sn + k0 + c];
            Vs[r][c] = Vb[(size_t)(k0 + r) * Dn + c];
        }
        __syncthreads();

        #pragma unroll 8
        for (int kk = 0; kk < 64; kk++) {
            float a[4], bv[4];
            #pragma unroll
            for (int i = 0; i < 4; i++) a[i]  = Ws[ty + i * 16][kk];
            #pragma unroll
            for (int j = 0; j < 4; j++) bv[j] = Vs[kk][tx + j * 16];
            #pragma unroll
            for (int i = 0; i < 4; i++)
                #pragma unroll
                for (int j = 0; j < 4; j++)
                    acc[i][j] = fmaf(a[i], bv[j], acc[i][j]);
        }
        __syncthreads();
    }

    float* Ob = O + ((size_t)bh * Sn + q0) * Dn;
    #pragma unroll
    for (int i = 0; i < 4; i++) {
        const int qr = ty + i * 16;
        #pragma unroll
        for (int j = 0; j < 4; j++) {
            Ob[(size_t)qr * Dn + tx + j * 16] = acc[i][j];
        }
    }
}

// ---------------------------------------------------------------------------
// Entry point
// ---------------------------------------------------------------------------
extern "C" void kernel_launch(void* const* d_in, const int* in_sizes, int n_in,
                              void* d_out, int out_size)
{
    const float* Q    = (const float*)d_in[0];
    const float* K    = (const float*)d_in[1];
    const float* V    = (const float*)d_in[2];
    const int*   mask = (const int*)  d_in[3];

    float* O = (float*)d_out;          // [B,H,S,D]
    float* W = O + OSZ;                // [B,H,S,S] attn_weights

    // 1) scores + mask
    {
        dim3 grid(Sn / 64, Sn / 64, BHn);
        dim3 block(16, 16);
        qk_scores_kernel<<<grid, block>>>(Q, K, mask, W);
    }
    // 2) softmax rows (in place on the weights region)
    {
        softmax_rows_kernel<<<BHn * Sn, 256>>>(W);
    }
    // 3) O = W @ V
    {
        dim3 grid(Sn / 64, BHn);
        dim3 block(16, 16);
        av_kernel<<<grid, block>>>(W, V, O);
    }
    (void)in_sizes; (void)n_in; (void)out_size;
}

// round 3
// speedup vs baseline: 2.5439x; 2.5439x over previous
#include <cuda_runtime.h>
#include <cuda_bf16.h>
#include <stdint.h>

#define Sn 2048
#define Dn 64
#define Hn 16
#define BHn 64

static const size_t OSZ = (size_t)BHn * Sn * Dn;
#define NEG_INF __int_as_float(0xff800000)

// ------------------------------------------------------------------ helpers
__device__ __forceinline__ uint32_t smem_u32(const void* p) {
    uint32_t a;
    asm("{ .reg .u64 t; cvta.to.shared.u64 t, %1; cvt.u32.u64 %0, t; }"
        : "=r"(a) : "l"(p));
    return a;
}

#define SW128(o) ((uint32_t)(o) ^ ((((uint32_t)(o)) >> 3) & 0x70))

__device__ __forceinline__ void ldsm_x4(uint32_t r[4], uint32_t addr) {
    asm volatile("ldmatrix.sync.aligned.m8n8.x4.shared.b16 {%0,%1,%2,%3}, [%4];"
                 : "=r"(r[0]), "=r"(r[1]), "=r"(r[2]), "=r"(r[3]) : "r"(addr));
}
__device__ __forceinline__ void ldsm_x4t(uint32_t r[4], uint32_t addr) {
    asm volatile("ldmatrix.sync.aligned.m8n8.x4.trans.shared.b16 {%0,%1,%2,%3}, [%4];"
                 : "=r"(r[0]), "=r"(r[1]), "=r"(r[2]), "=r"(r[3]) : "r"(addr));
}

__device__ __forceinline__ void mma16816(float c[4], const uint32_t a[4],
                                         uint32_t b0, uint32_t b1) {
    asm volatile(
        "mma.sync.aligned.m16n8k16.row.col.f32.bf16.bf16.f32 "
        "{%0,%1,%2,%3}, {%4,%5,%6,%7}, {%8,%9}, {%0,%1,%2,%3};"
        : "+f"(c[0]), "+f"(c[1]), "+f"(c[2]), "+f"(c[3])
        : "r"(a[0]), "r"(a[1]), "r"(a[2]), "r"(a[3]), "r"(b0), "r"(b1));
}

__device__ __forceinline__ void cvt_split(float x, uint16_t& h, uint16_t& l) {
    __nv_bfloat16 hb = __float2bfloat16_rn(x);
    float r = x - __bfloat162float(hb);
    __nv_bfloat16 lb = __float2bfloat16_rn(r);
    h = __bfloat16_as_ushort(hb);
    l = __bfloat16_as_ushort(lb);
}

// pack 4 floats -> hi/lo bf16 pair-words, store 8B each at swizzled offset
__device__ __forceinline__ void store_split4(char* smem_hi, char* smem_lo,
                                             uint32_t sw, float4 v) {
    uint16_t h0, l0, h1, l1, h2, l2, h3, l3;
    cvt_split(v.x, h0, l0); cvt_split(v.y, h1, l1);
    cvt_split(v.z, h2, l2); cvt_split(v.w, h3, l3);
    uint2 hw, lw;
    hw.x = (uint32_t)h0 | ((uint32_t)h1 << 16);
    hw.y = (uint32_t)h2 | ((uint32_t)h3 << 16);
    lw.x = (uint32_t)l0 | ((uint32_t)l1 << 16);
    lw.y = (uint32_t)l2 | ((uint32_t)l3 << 16);
    *(uint2*)(smem_hi + sw) = hw;
    *(uint2*)(smem_lo + sw) = lw;
}

// ---------------------------------------------------------------------------
// Kernel 1: W = mask ? -inf : (Q @ K^T) * 0.125
// Tile 128(q) x 128(k), K=64. 256 threads = 8 warps (4x2), warp tile 32x64.
// ---------------------------------------------------------------------------
__global__ void __launch_bounds__(256)
qk_kernel(const float* __restrict__ Q, const float* __restrict__ K,
          const int* __restrict__ mask, float* __restrict__ W) {
    extern __shared__ char smem[];
    const uint32_t sb = smem_u32(smem);
    const int tid = threadIdx.x, lid = tid & 31, wid = tid >> 5;
    const int warp_m = wid & 3, warp_n = wid >> 2;
    const int q0 = blockIdx.x * 128, k0 = blockIdx.y * 128, bh = blockIdx.z;
    const int b = bh / Hn;

    char* AH = smem;               // 128x64 bf16 (Q hi)
    char* AL = smem + 16384;       // Q lo
    char* KH = smem + 32768;       // K hi
    char* KL = smem + 49152;       // K lo
    int* mskS = (int*)(smem + 65536);

    if (tid < 128) mskS[tid] = mask[b * Sn + k0 + tid];

    const float4* Qt = (const float4*)(Q + ((size_t)bh * Sn + q0) * Dn);
    const float4* Kt = (const float4*)(K + ((size_t)bh * Sn + k0) * Dn);
    #pragma unroll
    for (int j = 0; j < 8; j++) {
        const int f = tid + j * 256;                     // float4 index (2048)
        const uint32_t sw = SW128((f >> 4) * 128 + (f & 15) * 8);
        store_split4(AH, AL, sw, Qt[f]);
        store_split4(KH, KL, sw, Kt[f]);
    }
    __syncthreads();

    float acc[16][4];   // [mt*8 + nt][frag], mt 0..1, nt 0..7 (n8 tiles)
    #pragma unroll
    for (int i = 0; i < 16; i++)
        #pragma unroll
        for (int j = 0; j < 4; j++) acc[i][j] = 0.0f;

    #pragma unroll
    for (int ks = 0; ks < 4; ks++) {
        uint32_t aH[2][4], aL[2][4];
        #pragma unroll
        for (int mt = 0; mt < 2; mt++) {
            const uint32_t off = (uint32_t)(warp_m * 32 + mt * 16 + (lid & 15)) * 128
                               + ks * 32 + (lid >> 4) * 16;
            ldsm_x4(aH[mt], sb + SW128(off));
            ldsm_x4(aL[mt], sb + 16384 + SW128(off));
        }
        #pragma unroll
        for (int ng = 0; ng < 4; ng++) {
            const uint32_t boff = (uint32_t)(warp_n * 64 + ng * 16 + (lid & 15)) * 128
                                + ks * 32 + (lid >> 4) * 16;
            uint32_t bHf[4], bLf[4];
            ldsm_x4(bHf, sb + 32768 + SW128(boff));
            ldsm_x4(bLf, sb + 49152 + SW128(boff));
            #pragma unroll
            for (int mt = 0; mt < 2; mt++) {
                float* c0 = acc[mt * 8 + ng * 2 + 0];
                float* c1 = acc[mt * 8 + ng * 2 + 1];
                // n-tile even: b regs (r0, r2); odd: (r1, r3)
                mma16816(c0, aH[mt], bHf[0], bHf[2]);
                mma16816(c0, aL[mt], bHf[0], bHf[2]);
                mma16816(c0, aH[mt], bLf[0], bLf[2]);
                mma16816(c1, aH[mt], bHf[1], bHf[3]);
                mma16816(c1, aL[mt], bHf[1], bHf[3]);
                mma16816(c1, aH[mt], bLf[1], bLf[3]);
            }
        }
    }

    // Epilogue: scale + mask, direct float2 stores
    float* Wb = W + (size_t)bh * Sn * Sn;
    #pragma unroll
    for (int mt = 0; mt < 2; mt++) {
        #pragma unroll
        for (int nt = 0; nt < 8; nt++) {
            const float* c = acc[mt * 8 + nt];
            const int row = q0 + warp_m * 32 + mt * 16 + (lid >> 2);
            const int colL = warp_n * 64 + nt * 8 + (lid & 3) * 2;
            const int m0 = mskS[colL], m1 = mskS[colL + 1];
            float2 v0, v1;
            v0.x = m0 ? NEG_INF : c[0] * 0.125f;
            v0.y = m1 ? NEG_INF : c[1] * 0.125f;
            v1.x = m0 ? NEG_INF : c[2] * 0.125f;
            v1.y = m1 ? NEG_INF : c[3] * 0.125f;
            *(float2*)(Wb + (size_t)row * Sn + k0 + colL) = v0;
            *(float2*)(Wb + (size_t)(row + 8) * Sn + k0 + colL) = v1;
        }
    }
}

// ---------------------------------------------------------------------------
// Kernel 2: row softmax over last dim (2048), in place, vectorized.
// ---------------------------------------------------------------------------
__global__ void softmax_rows_kernel(float* __restrict__ W) {
    float4* p = (float4*)(W + (size_t)blockIdx.x * Sn);
    const int t = threadIdx.x;               // 256 threads
    const int w = t >> 5, l = t & 31;
    __shared__ float red[8];

    float4 a = p[t], b = p[t + 256];
    float mx = fmaxf(fmaxf(fmaxf(a.x, a.y), fmaxf(a.z, a.w)),
                     fmaxf(fmaxf(b.x, b.y), fmaxf(b.z, b.w)));
    #pragma unroll
    for (int s = 16; s > 0; s >>= 1) mx = fmaxf(mx, __shfl_xor_sync(0xffffffffu, mx, s));
    if (l == 0) red[w] = mx;
    __syncthreads();
    mx = fmaxf(fmaxf(fmaxf(red[0], red[1]), fmaxf(red[2], red[3])),
               fmaxf(fmaxf(red[4], red[5]), fmaxf(red[6], red[7])));
    __syncthreads();

    a.x = expf(a.x - mx); a.y = expf(a.y - mx); a.z = expf(a.z - mx); a.w = expf(a.w - mx);
    b.x = expf(b.x - mx); b.y = expf(b.y - mx); b.z = expf(b.z - mx); b.w = expf(b.w - mx);
    float sum = (a.x + a.y) + (a.z + a.w) + (b.x + b.y) + (b.z + b.w);
    #pragma unroll
    for (int s = 16; s > 0; s >>= 1) sum += __shfl_xor_sync(0xffffffffu, sum, s);
    if (l == 0) red[w] = sum;
    __syncthreads();
    sum = ((red[0] + red[1]) + (red[2] + red[3])) + ((red[4] + red[5]) + (red[6] + red[7]));
    const float inv = 1.0f / sum;

    a.x *= inv; a.y *= inv; a.z *= inv; a.w *= inv;
    b.x *= inv; b.y *= inv; b.z *= inv; b.w *= inv;
    p[t] = a; p[t + 256] = b;
}

// ---------------------------------------------------------------------------
// Kernel 3: O = P @ V.  Tile 128(q) x 64(d), k-loop 32 chunks of 64.
// 256 threads = 8 warps (4x2), warp tile 32x32.
// ---------------------------------------------------------------------------
__global__ void __launch_bounds__(256)
av_kernel(const float* __restrict__ P, const float* __restrict__ V,
          float* __restrict__ O) {
    extern __shared__ char smem[];
    const uint32_t sb = smem_u32(smem);
    const int tid = threadIdx.x, lid = tid & 31, wid = tid >> 5;
    const int warp_m = wid & 3, warp_n = wid >> 2;
    const int q0 = blockIdx.x * 128, bh = blockIdx.y;

    char* PH = smem;               // 128x64 bf16
    char* PL = smem + 16384;
    char* VH = smem + 32768;       // 64x64 bf16
    char* VL = smem + 40960;

    const float* Pb = P + (size_t)bh * Sn * Sn + (size_t)q0 * Sn;
    const float* Vb = V + (size_t)bh * Sn * Dn;

    float acc[8][4];   // [mt*4 + nt][frag], mt 0..1, nt 0..3
    #pragma unroll
    for (int i = 0; i < 8; i++)
        #pragma unroll
        for (int j = 0; j < 4; j++) acc[i][j] = 0.0f;

    for (int kc = 0; kc < Sn; kc += 64) {
        #pragma unroll
        for (int j = 0; j < 8; j++) {        // P tile 128x64
            const int f = tid + j * 256;
            const int row = f >> 4, colf = (f & 15) * 4;
            float4 v = *(const float4*)(Pb + (size_t)row * Sn + kc + colf);
            store_split4(PH, PL, SW128(row * 128 + colf * 2), v);
        }
        #pragma unroll
        for (int j = 0; j < 4; j++) {        // V tile 64x64
            const int f = tid + j * 256;
            const int row = f >> 4, colf = (f & 15) * 4;
            float4 v = *(const float4*)(Vb + (size_t)(kc + row) * Dn + colf);
            store_split4(VH, VL, SW128(row * 128 + colf * 2), v);
        }
        __syncthreads();

        #pragma unroll
        for (int ks = 0; ks < 4; ks++) {
            uint32_t aH[2][4], aL[2][4];
            #pragma unroll
            for (int mt = 0; mt < 2; mt++) {
                const uint32_t off = (uint32_t)(warp_m * 32 + mt * 16 + (lid & 15)) * 128
                                   + ks * 32 + (lid >> 4) * 16;
                ldsm_x4(aH[mt], sb + SW128(off));
                ldsm_x4(aL[mt], sb + 16384 + SW128(off));
            }
            #pragma unroll
            for (int ng = 0; ng < 2; ng++) {
                // V^T fragments: rows k, cols n. trans load.
                const uint32_t voff =
                    (uint32_t)(ks * 16 + (lid & 7) + ((lid >> 3) & 1) * 8) * 128
                    + (warp_n * 32 + ng * 16 + (lid >> 4) * 8) * 2;
                uint32_t bHf[4], bLf[4];
                ldsm_x4t(bHf, sb + 32768 + SW128(voff));
                ldsm_x4t(bLf, sb + 40960 + SW128(voff));
                #pragma unroll
                for (int mt = 0; mt < 2; mt++) {
                    float* c0 = acc[mt * 4 + ng * 2 + 0];
                    float* c1 = acc[mt * 4 + ng * 2 + 1];
                    // trans tiles: even n-tile (r0,r1), odd (r2,r3)
                    mma16816(c0, aH[mt], bHf[0], bHf[1]);
                    mma16816(c0, aL[mt], bHf[0], bHf[1]);
                    mma16816(c0, aH[mt], bLf[0], bLf[1]);
                    mma16816(c1, aH[mt], bHf[2], bHf[3]);
                    mma16816(c1, aL[mt], bHf[2], bHf[3]);
                    mma16816(c1, aH[mt], bLf[2], bLf[3]);
                }
            }
        }
        __syncthreads();
    }

    float* Ob = O + ((size_t)bh * Sn + q0) * Dn;
    #pragma unroll
    for (int mt = 0; mt < 2; mt++) {
        #pragma unroll
        for (int nt = 0; nt < 4; nt++) {
            const float* c = acc[mt * 4 + nt];
            const int row = warp_m * 32 + mt * 16 + (lid >> 2);
            const int col = warp_n * 32 + nt * 8 + (lid & 3) * 2;
            *(float2*)(Ob + (size_t)row * Dn + col) = make_float2(c[0], c[1]);
            *(float2*)(Ob + (size_t)(row + 8) * Dn + col) = make_float2(c[2], c[3]);
        }
    }
}

// ---------------------------------------------------------------------------
extern "C" void kernel_launch(void* const* d_in, const int* in_sizes, int n_in,
                              void* d_out, int out_size) {
    const float* Q    = (const float*)d_in[0];
    const float* K    = (const float*)d_in[1];
    const float* V    = (const float*)d_in[2];
    const int*   mask = (const int*)  d_in[3];

    float* O = (float*)d_out;
    float* W = O + OSZ;

    static const int QK_SMEM = 65536 + 512;   // tiles + mask
    static const int AV_SMEM = 49152;

    cudaFuncSetAttribute(qk_kernel, cudaFuncAttributeMaxDynamicSharedMemorySize, QK_SMEM);
    cudaFuncSetAttribute(av_kernel, cudaFuncAttributeMaxDynamicSharedMemorySize, AV_SMEM);

    {
        dim3 grid(Sn / 128, Sn / 128, BHn);
        qk_kernel<<<grid, 256, QK_SMEM>>>(Q, K, mask, W);
    }
    softmax_rows_kernel<<<BHn * Sn, 256>>>(W);
    {
        dim3 grid(Sn / 128, BHn);
        av_kernel<<<grid, 256, AV_SMEM>>>(W, V, O);
    }
    (void)in_sizes; (void)n_in; (void)out_size;
}